// round 2
// baseline (speedup 1.0000x reference)
#include <cuda_runtime.h>
#include <cstddef>

// ---------------- problem constants ----------------
#define B_  32
#define L_  512
#define E_  768
#define F_  512
#define M_  (B_ * L_)          // 16384 rows
#define EPSF 1e-7f

// ---------------- d_out layout (floats) ----------------
#define OFF_APRED 0L
#define OFF_OPRED 49152L
#define OFF_SPRED 98304L
#define OFF_AINT  147456L      // [B,L,1024]
#define OFF_OINT  16924672L    // [B,L,1024]
#define OFF_CINT  33701888L    // [B,L,768]
#define OFF_CCONV 46284800L    // [B,L,768]

// ---------------- device scratch ----------------
__device__ float g_aconv[(size_t)M_ * F_];            // 32 MB
__device__ float g_oconv[(size_t)M_ * F_];            // 32 MB
__device__ float g_G [(size_t)B_ * L_ * L_];          // 32 MB (gram / expG, reused as WS0)
__device__ float g_A1[(size_t)B_ * L_ * L_];          // 32 MB
__device__ float g_A2[(size_t)B_ * L_ * L_];          // 32 MB (reused as WS / word_attend)
__device__ float g_inva[M_], g_invo[M_], g_invc[M_];
__device__ float g_rowsum[M_], g_colsum[M_], g_colsumP[M_];
__device__ float g_msum[B_];
__device__ float g_conf[M_];

// =====================================================================
// Conv1d(K=3, SAME) + bias + relu as GEMM:  [M x 2304] @ [2304 x N]
// A is gathered from x with per-tap shift; 768 % 8 == 0 so a BK=8 tile
// never crosses a tap boundary.
// =====================================================================
__global__ __launch_bounds__(256) void conv_gemm(
    const float* __restrict__ X, const float* __restrict__ W,
    const float* __restrict__ bias,
    float* __restrict__ C1, int ldc1,
    float* __restrict__ C2, int ldc2, int N)
{
    __shared__ float As[8 * 128];
    __shared__ float Bs[8 * 128];
    const int tid = threadIdx.x;
    const int tx = tid & 15, ty = tid >> 4;
    const int m0 = blockIdx.x * 128;
    const int n0 = blockIdx.y * 128;

    const int arow  = tid >> 1;
    const int ahalf = (tid & 1) * 4;
    const int gm_a  = m0 + arow;
    const int b = gm_a >> 9, l = gm_a & 511;

    const int brow = tid >> 5;
    const int bcol = (tid & 31) * 4;

    float acc[8][8];
#pragma unroll
    for (int i = 0; i < 8; i++)
#pragma unroll
        for (int j = 0; j < 8; j++) acc[i][j] = 0.f;

    for (int kt = 0; kt < 288; ++kt) {
        const int k0  = kt * 8;
        const int tap = k0 / 768;
        const int e0  = k0 - tap * 768;
        const int src = l + tap - 1;

        float4 av = make_float4(0.f, 0.f, 0.f, 0.f);
        if (src >= 0 && src < L_)
            av = *reinterpret_cast<const float4*>(
                X + ((size_t)(b * L_ + src)) * E_ + e0 + ahalf);
        float4 bv = *reinterpret_cast<const float4*>(
            W + ((size_t)(k0 + brow)) * N + n0 + bcol);

        __syncthreads();
        As[(ahalf + 0) * 128 + arow] = av.x;
        As[(ahalf + 1) * 128 + arow] = av.y;
        As[(ahalf + 2) * 128 + arow] = av.z;
        As[(ahalf + 3) * 128 + arow] = av.w;
        *reinterpret_cast<float4*>(Bs + brow * 128 + bcol) = bv;
        __syncthreads();

#pragma unroll
        for (int k = 0; k < 8; k++) {
            float a[8], bb[8];
            *reinterpret_cast<float4*>(a)     = *reinterpret_cast<const float4*>(As + k * 128 + ty * 8);
            *reinterpret_cast<float4*>(a + 4) = *reinterpret_cast<const float4*>(As + k * 128 + ty * 8 + 4);
            *reinterpret_cast<float4*>(bb)     = *reinterpret_cast<const float4*>(Bs + k * 128 + tx * 8);
            *reinterpret_cast<float4*>(bb + 4) = *reinterpret_cast<const float4*>(Bs + k * 128 + tx * 8 + 4);
#pragma unroll
            for (int i = 0; i < 8; i++)
#pragma unroll
                for (int j = 0; j < 8; j++)
                    acc[i][j] = fmaf(a[i], bb[j], acc[i][j]);
        }
    }

#pragma unroll
    for (int i = 0; i < 8; i++) {
        const int gm = m0 + ty * 8 + i;
#pragma unroll
        for (int j = 0; j < 8; j++) {
            const int gn = n0 + tx * 8 + j;
            float v = fmaxf(acc[i][j] + bias[gn], 0.f);
            C1[(size_t)gm * ldc1 + gn] = v;
            if (C2) C2[(size_t)gm * ldc2 + gn] = v;
        }
    }
}

// =====================================================================
// Batched NT GEMM: C[b,i,j] = (A[b,i,:] . Bv[b,j,:]) * rs[b,i] * cs[b,j]
// A,Bv: [B,512,K] row-major. C: [B,512,512]. rs/cs nullable.
// =====================================================================
__global__ __launch_bounds__(256) void gemm_nt(
    const float* __restrict__ Aa, const float* __restrict__ Bv,
    float* __restrict__ C,
    const float* __restrict__ rs, const float* __restrict__ cs, int K)
{
    __shared__ float As[8 * 128];
    __shared__ float Bs[8 * 128];
    const int tid = threadIdx.x;
    const int tx = tid & 15, ty = tid >> 4;
    const int bz = blockIdx.z;
    const int m0 = blockIdx.x * 128, n0 = blockIdx.y * 128;
    const float* Ab = Aa + (size_t)bz * L_ * K;
    const float* Bb = Bv + (size_t)bz * L_ * K;

    const int arow  = tid >> 1;
    const int ahalf = (tid & 1) * 4;

    float acc[8][8];
#pragma unroll
    for (int i = 0; i < 8; i++)
#pragma unroll
        for (int j = 0; j < 8; j++) acc[i][j] = 0.f;

    for (int k0 = 0; k0 < K; k0 += 8) {
        float4 av = *reinterpret_cast<const float4*>(Ab + (size_t)(m0 + arow) * K + k0 + ahalf);
        float4 bv = *reinterpret_cast<const float4*>(Bb + (size_t)(n0 + arow) * K + k0 + ahalf);
        __syncthreads();
        As[(ahalf + 0) * 128 + arow] = av.x;
        As[(ahalf + 1) * 128 + arow] = av.y;
        As[(ahalf + 2) * 128 + arow] = av.z;
        As[(ahalf + 3) * 128 + arow] = av.w;
        Bs[(ahalf + 0) * 128 + arow] = bv.x;
        Bs[(ahalf + 1) * 128 + arow] = bv.y;
        Bs[(ahalf + 2) * 128 + arow] = bv.z;
        Bs[(ahalf + 3) * 128 + arow] = bv.w;
        __syncthreads();
#pragma unroll
        for (int k = 0; k < 8; k++) {
            float a[8], bb[8];
            *reinterpret_cast<float4*>(a)     = *reinterpret_cast<const float4*>(As + k * 128 + ty * 8);
            *reinterpret_cast<float4*>(a + 4) = *reinterpret_cast<const float4*>(As + k * 128 + ty * 8 + 4);
            *reinterpret_cast<float4*>(bb)     = *reinterpret_cast<const float4*>(Bs + k * 128 + tx * 8);
            *reinterpret_cast<float4*>(bb + 4) = *reinterpret_cast<const float4*>(Bs + k * 128 + tx * 8 + 4);
#pragma unroll
            for (int i = 0; i < 8; i++)
#pragma unroll
                for (int j = 0; j < 8; j++)
                    acc[i][j] = fmaf(a[i], bb[j], acc[i][j]);
        }
    }

#pragma unroll
    for (int i = 0; i < 8; i++) {
        const int mi = m0 + ty * 8 + i;
        const float rsc = rs ? rs[bz * L_ + mi] : 1.f;
#pragma unroll
        for (int j = 0; j < 8; j++) {
            const int nj = n0 + tx * 8 + j;
            const float csc = cs ? cs[bz * L_ + nj] : 1.f;
            C[(size_t)bz * L_ * L_ + (size_t)mi * L_ + nj] = acc[i][j] * rsc * csc;
        }
    }
}

// =====================================================================
// Batched NN GEMM: C[(b*512+i)*ldc + n] = A[b,i,:] @ Bm[b,:,n] (+ add row)
// A: [B,512,K], Bm: [B,K,N]. C base may include a column offset.
// =====================================================================
__global__ __launch_bounds__(256) void gemm_nn(
    const float* __restrict__ Aa, const float* __restrict__ Bm,
    float* __restrict__ C, const float* __restrict__ addp,
    int K, int N, int ldc)
{
    __shared__ float As[8 * 128];
    __shared__ float Bs[8 * 128];
    const int tid = threadIdx.x;
    const int tx = tid & 15, ty = tid >> 4;
    const int bz = blockIdx.z;
    const int m0 = blockIdx.x * 128, n0 = blockIdx.y * 128;
    const float* Ab = Aa + (size_t)bz * L_ * K;
    const float* Bb = Bm + (size_t)bz * K * N;

    const int arow  = tid >> 1;
    const int ahalf = (tid & 1) * 4;
    const int brow = tid >> 5;
    const int bcol = (tid & 31) * 4;

    float acc[8][8];
#pragma unroll
    for (int i = 0; i < 8; i++)
#pragma unroll
        for (int j = 0; j < 8; j++) acc[i][j] = 0.f;

    for (int k0 = 0; k0 < K; k0 += 8) {
        float4 av = *reinterpret_cast<const float4*>(Ab + (size_t)(m0 + arow) * K + k0 + ahalf);
        float4 bv = *reinterpret_cast<const float4*>(Bb + (size_t)(k0 + brow) * N + n0 + bcol);
        __syncthreads();
        As[(ahalf + 0) * 128 + arow] = av.x;
        As[(ahalf + 1) * 128 + arow] = av.y;
        As[(ahalf + 2) * 128 + arow] = av.z;
        As[(ahalf + 3) * 128 + arow] = av.w;
        *reinterpret_cast<float4*>(Bs + brow * 128 + bcol) = bv;
        __syncthreads();
#pragma unroll
        for (int k = 0; k < 8; k++) {
            float a[8], bb[8];
            *reinterpret_cast<float4*>(a)     = *reinterpret_cast<const float4*>(As + k * 128 + ty * 8);
            *reinterpret_cast<float4*>(a + 4) = *reinterpret_cast<const float4*>(As + k * 128 + ty * 8 + 4);
            *reinterpret_cast<float4*>(bb)     = *reinterpret_cast<const float4*>(Bs + k * 128 + tx * 8);
            *reinterpret_cast<float4*>(bb + 4) = *reinterpret_cast<const float4*>(Bs + k * 128 + tx * 8 + 4);
#pragma unroll
            for (int i = 0; i < 8; i++)
#pragma unroll
                for (int j = 0; j < 8; j++)
                    acc[i][j] = fmaf(a[i], bb[j], acc[i][j]);
        }
    }

#pragma unroll
    for (int i = 0; i < 8; i++) {
        const size_t grow = (size_t)bz * L_ + m0 + ty * 8 + i;
#pragma unroll
        for (int j = 0; j < 8; j++) {
            const int nj = n0 + tx * 8 + j;
            float v = acc[i][j];
            if (addp) v += addp[grow * N + nj];
            C[grow * ldc + nj] = v;
        }
    }
}

// ---------------- row inverse l2 norm ----------------
__global__ void rowinv_k(const float* __restrict__ X, int D, float* __restrict__ inv)
{
    const int m = blockIdx.x, t = threadIdx.x;   // 256 threads
    float s = 0.f;
    for (int k = t; k < D; k += 256) { float v = X[(size_t)m * D + k]; s = fmaf(v, v, s); }
    __shared__ float red[256];
    red[t] = s; __syncthreads();
    for (int st = 128; st > 0; st >>= 1) { if (t < st) red[t] += red[t + st]; __syncthreads(); }
    if (t == 0) inv[m] = rsqrtf(fmaxf(red[0], 1e-12f));
}

// ---------------- exp(G) in place + masked row sums ----------------
__global__ void exp_rowsum_k(const float* __restrict__ mask)
{
    const int row = blockIdx.x, t = threadIdx.x;  // 512 threads
    const int b = row >> 9;
    const size_t idx = (size_t)row * L_ + t;
    float e = expf(g_G[idx]);
    g_G[idx] = e;
    float v = e * mask[b * L_ + t];
    __shared__ float red[512];
    red[t] = v; __syncthreads();
    for (int st = 256; st > 0; st >>= 1) { if (t < st) red[t] += red[t + st]; __syncthreads(); }
    if (t == 0) g_rowsum[row] = red[0];
}

// ---------------- deterministic column sums (optionally row-weighted) --
__global__ void colsum_k(const float* __restrict__ src, const float* __restrict__ wmask,
                         float* __restrict__ dst)
{
    const int b = blockIdx.x, c = blockIdx.y * 128 + threadIdx.x;
    const float* S = src + (size_t)b * L_ * L_;
    float acc = 0.f;
#pragma unroll 4
    for (int r = 0; r < L_; r++) {
        float w = wmask ? wmask[b * L_ + r] : 1.f;
        acc = fmaf(S[(size_t)r * L_ + c], w, acc);
    }
    dst[b * L_ + c] = acc;
}

// ---------------- A1 (row-softmask) + A2 (col-softmask, transposed) ----
__global__ void a12_k(const float* __restrict__ mask)
{
    __shared__ float s[32][33];
    const int b = blockIdx.z;
    const int i0 = blockIdx.y * 32, j0 = blockIdx.x * 32;
    const int tx = threadIdx.x, ty = threadIdx.y;
    const float* Eb = g_G + (size_t)b * L_ * L_;
    const float* mk = mask + b * L_;
    s[ty][tx] = Eb[(size_t)(i0 + ty) * L_ + j0 + tx];
    __syncthreads();
    float a1 = s[ty][tx] * mk[j0 + tx] / (g_rowsum[b * L_ + i0 + ty] + EPSF) * mk[i0 + ty];
    g_A1[(size_t)b * L_ * L_ + (size_t)(i0 + ty) * L_ + j0 + tx] = a1;
    // A2[p,q] = expG[q,p]*mask[q]/(colsum[p]+eps)*mask[p] with p=j0+ty, q=i0+tx
    float a2 = s[tx][ty] * mk[i0 + tx] / (g_colsum[b * L_ + j0 + ty] + EPSF) * mk[j0 + ty];
    g_A2[(size_t)b * L_ * L_ + (size_t)(j0 + ty) * L_ + i0 + tx] = a2;
}

// ---------------- dense [D]->3 head (+ optional confidence) -----------
__global__ void pred3_k(const float* __restrict__ X, int D,
                        const float* __restrict__ Wd, const float* __restrict__ bd,
                        float* __restrict__ out, float* __restrict__ conf)
{
    const int m = blockIdx.x, t = threadIdx.x;   // 128 threads
    const float* xr = X + (size_t)m * D;
    float a0 = 0.f, a1 = 0.f, a2 = 0.f;
    for (int k = t; k < D; k += 128) {
        float x = xr[k];
        a0 = fmaf(x, Wd[3 * k + 0], a0);
        a1 = fmaf(x, Wd[3 * k + 1], a1);
        a2 = fmaf(x, Wd[3 * k + 2], a2);
    }
#pragma unroll
    for (int o = 16; o > 0; o >>= 1) {
        a0 += __shfl_down_sync(0xffffffffu, a0, o);
        a1 += __shfl_down_sync(0xffffffffu, a1, o);
        a2 += __shfl_down_sync(0xffffffffu, a2, o);
    }
    __shared__ float sh[4][3];
    const int w = t >> 5, ln = t & 31;
    if (ln == 0) { sh[w][0] = a0; sh[w][1] = a1; sh[w][2] = a2; }
    __syncthreads();
    if (t == 0) {
        float p0 = sh[0][0] + sh[1][0] + sh[2][0] + sh[3][0] + bd[0];
        float p1 = sh[0][1] + sh[1][1] + sh[2][1] + sh[3][1] + bd[1];
        float p2 = sh[0][2] + sh[1][2] + sh[2][2] + sh[3][2] + bd[2];
        out[(size_t)m * 3 + 0] = p0;
        out[(size_t)m * 3 + 1] = p1;
        out[(size_t)m * 3 + 2] = p2;
        if (conf) {
            float mx = fmaxf(p0, fmaxf(p1, p2));
            float e0 = expf(p0 - mx), e1 = expf(p1 - mx), e2 = expf(p2 - mx);
            conf[m] = fmaxf(0.f, 1.f - 2.f * e0 / (e0 + e1 + e2));
        }
    }
}

// ---------------- per-batch mask sums ----------------
__global__ void msum_k(const float* __restrict__ mask)
{
    const int b = blockIdx.x, t = threadIdx.x;   // 512 threads
    __shared__ float red[512];
    red[t] = mask[b * L_ + t]; __syncthreads();
    for (int st = 256; st > 0; st >>= 1) { if (t < st) red[t] += red[t + st]; __syncthreads(); }
    if (t == 0) g_msum[b] = red[0];
}

// ---- softmask(WS, scale=True) + A1 + conf*msum*colsumP, in place ------
__global__ void smax_combine_k(const float* __restrict__ mask)
{
    const int row = blockIdx.x, t = threadIdx.x;  // 512 threads
    const int b = row >> 9, i = row & 511;
    const size_t base = (size_t)row * L_;
    float v = g_A2[base + t];
    __shared__ float red[512];
    red[t] = v; __syncthreads();
    for (int st = 256; st > 0; st >>= 1) { if (t < st) red[t] = fmaxf(red[t], red[t + st]); __syncthreads(); }
    const float mx = red[0]; __syncthreads();
    float e = expf(v - mx) * mask[b * L_ + t];
    red[t] = e; __syncthreads();
    for (int st = 256; st > 0; st >>= 1) { if (t < st) red[t] += red[t + st]; __syncthreads(); }
    const float sum = red[0];
    float att = e / (sum + EPSF) * mask[b * L_ + i];
    g_A2[base + t] = att + g_A1[base + t] + g_conf[row] * g_msum[b] * g_colsumP[b * L_ + t];
}

// =====================================================================
extern "C" void kernel_launch(void* const* d_in, const int* in_sizes, int n_in,
                              void* d_out, int out_size)
{
    const float* aspect_in  = (const float*)d_in[0];
    const float* opinion_in = (const float*)d_in[1];
    const float* context_in = (const float*)d_in[2];
    const float* cq         = (const float*)d_in[3];
    const float* mask       = (const float*)d_in[4];
    const float* pos        = (const float*)d_in[5];
    const float* Wa  = (const float*)d_in[6];
    const float* ba  = (const float*)d_in[7];
    const float* Wo  = (const float*)d_in[8];
    const float* bo  = (const float*)d_in[9];
    const float* Wc  = (const float*)d_in[10];
    const float* bc  = (const float*)d_in[11];
    const float* Wda = (const float*)d_in[12];
    const float* bda = (const float*)d_in[13];
    const float* Wdo = (const float*)d_in[14];
    const float* bdo = (const float*)d_in[15];
    const float* Wds = (const float*)d_in[16];
    const float* bds = (const float*)d_in[17];
    float* out = (float*)d_out;

    float *aconv, *oconv, *G, *A1, *A2, *inva, *invo, *invc, *colsumP, *conf;
    cudaGetSymbolAddress((void**)&aconv,   g_aconv);
    cudaGetSymbolAddress((void**)&oconv,   g_oconv);
    cudaGetSymbolAddress((void**)&G,       g_G);
    cudaGetSymbolAddress((void**)&A1,      g_A1);
    cudaGetSymbolAddress((void**)&A2,      g_A2);
    cudaGetSymbolAddress((void**)&inva,    g_inva);
    cudaGetSymbolAddress((void**)&invo,    g_invo);
    cudaGetSymbolAddress((void**)&invc,    g_invc);
    cudaGetSymbolAddress((void**)&colsumP, g_colsumP);
    cudaGetSymbolAddress((void**)&conf,    g_conf);
    float* colsum; cudaGetSymbolAddress((void**)&colsum, g_colsum);

    // ---- convolutions (write conv halves of interacts / context_conv) ----
    conv_gemm<<<dim3(128, 4), 256>>>(aspect_in,  Wa, ba, aconv, F_, out + OFF_AINT, 1024, F_);
    conv_gemm<<<dim3(128, 4), 256>>>(opinion_in, Wo, bo, oconv, F_, out + OFF_OINT, 1024, F_);
    conv_gemm<<<dim3(128, 6), 256>>>(context_in, Wc, bc, out + OFF_CCONV, E_, nullptr, 0, E_);

    // ---- inverse l2 norms ----
    rowinv_k<<<M_, 256>>>(aconv, F_, inva);
    rowinv_k<<<M_, 256>>>(oconv, F_, invo);
    rowinv_k<<<M_, 256>>>(out + OFF_CCONV, E_, invc);

    // ---- gram + bidirectional softmasks ----
    gemm_nt<<<dim3(4, 4, B_), 256>>>(aconv, oconv, G, inva, invo, F_);
    exp_rowsum_k<<<M_, 512>>>(mask);
    colsum_k<<<dim3(B_, 4), 128>>>(G, mask, colsum);
    a12_k<<<dim3(16, 16, B_), dim3(32, 32)>>>(mask);

    // ---- attention-weighted halves of interacts ----
    gemm_nn<<<dim3(4, 4, B_), 256>>>(A1, oconv, out + OFF_AINT + 512, nullptr, 512, 512, 1024);
    gemm_nn<<<dim3(4, 4, B_), 256>>>(A2, aconv, out + OFF_OINT + 512, nullptr, 512, 512, 1024);

    // ---- prediction heads + opinion confidence ----
    pred3_k<<<M_, 128>>>(out + OFF_AINT, 1024, Wda, bda, out + OFF_APRED, nullptr);
    pred3_k<<<M_, 128>>>(out + OFF_OINT, 1024, Wdo, bdo, out + OFF_OPRED, conf);

    // ---- collapsed opinion propagation terms ----
    colsum_k<<<dim3(B_, 4), 128>>>(pos, nullptr, colsumP);
    msum_k<<<B_, 512>>>(mask);

    // ---- context attention ----
    gemm_nt<<<dim3(4, 4, B_), 256>>>(cq, out + OFF_CCONV, G, nullptr, invc, E_);   // WS0 -> G
    gemm_nn<<<dim3(4, 4, B_), 256>>>(G, pos, A2, nullptr, 512, 512, 512);          // WS  -> A2
    smax_combine_k<<<M_, 512>>>(mask);                                             // word_attend -> A2
    gemm_nn<<<dim3(4, 6, B_), 256>>>(A2, out + OFF_CCONV, out + OFF_CINT, cq, 512, E_, E_);
    pred3_k<<<M_, 128>>>(out + OFF_CINT, E_, Wds, bds, out + OFF_SPRED, nullptr);
}

// round 4
// speedup vs baseline: 1.9922x; 1.9922x over previous
#include <cuda_runtime.h>
#include <cuda_bf16.h>
#include <cstdint>
#include <cstddef>

#define B_  32
#define L_  512
#define E_  768
#define F_  512
#define M_  (B_ * L_)
#define EPSF 1e-7f

#define OFF_APRED 0L
#define OFF_OPRED 49152L
#define OFF_SPRED 98304L
#define OFF_AINT  147456L
#define OFF_OINT  16924672L
#define OFF_CINT  33701888L
#define OFF_CCONV 46284800L

__device__ float g_aconv [(size_t)M_ * F_];
__device__ float g_oconv [(size_t)M_ * F_];
__device__ float g_aconvT[(size_t)M_ * F_];
__device__ float g_oconvT[(size_t)M_ * F_];
__device__ float g_cconvT[(size_t)B_ * E_ * L_];
__device__ float g_posT [(size_t)B_ * L_ * L_];
__device__ float g_WaT[(size_t)F_ * 3 * E_];
__device__ float g_WoT[(size_t)F_ * 3 * E_];
__device__ float g_WcT[(size_t)E_ * 3 * E_];
__device__ float g_G [(size_t)B_ * L_ * L_];
__device__ float g_A1[(size_t)B_ * L_ * L_];
__device__ float g_A2[(size_t)B_ * L_ * L_];
__device__ float g_inva[M_], g_invo[M_], g_invc[M_];
__device__ float g_rowsum[M_], g_colsum[M_], g_colsumP[M_];
__device__ float g_msum[B_];
__device__ float g_conf[M_];

// ---------------- helpers ----------------
__device__ __forceinline__ uint32_t su32(const void* p) {
    uint32_t a;
    asm("{ .reg .u64 t; cvta.to.shared.u64 t, %1; cvt.u32.u64 %0, t; }" : "=r"(a) : "l"(p));
    return a;
}
__device__ __forceinline__ void ldm_x4(uint32_t* r, uint32_t addr) {
    asm volatile("ldmatrix.sync.aligned.m8n8.x4.shared.b16 {%0,%1,%2,%3}, [%4];"
                 : "=r"(r[0]), "=r"(r[1]), "=r"(r[2]), "=r"(r[3]) : "r"(addr));
}
__device__ __forceinline__ void mma_bf16(float* c, const uint32_t* a, const uint32_t* b) {
    asm volatile(
        "mma.sync.aligned.m16n8k16.row.col.f32.bf16.bf16.f32 "
        "{%0,%1,%2,%3}, {%4,%5,%6,%7}, {%8,%9}, {%0,%1,%2,%3};"
        : "+f"(c[0]), "+f"(c[1]), "+f"(c[2]), "+f"(c[3])
        : "r"(a[0]), "r"(a[1]), "r"(a[2]), "r"(a[3]), "r"(b[0]), "r"(b[1]));
}
__device__ __forceinline__ uint32_t pk2(float x, float y) {
    __nv_bfloat162 t = __floats2bfloat162_rn(x, y);
    return *reinterpret_cast<uint32_t*>(&t);
}
__device__ __forceinline__ float bfhi(float x) {
    return __bfloat162float(__float2bfloat16_rn(x));
}

// ---------------- bf16x3 tensor-core GEMM ----------------
// C[128x128] = A(row-major,K) @ B(row-major N x K)^T, fp32 accum.
// GATHER: A rows gathered from X[B,512,768] with conv tap shift (K=2304).
#define ROWB 80
#define TILEB (128 * ROWB)
#define S_ALO TILEB
#define S_BHI (2 * TILEB)
#define S_BLO (3 * TILEB)
#define STAGE (4 * TILEB)
#define SMEM_DYN (2 * STAGE)

template<bool GATHER>
__global__ __launch_bounds__(256)
void tc_gemm(const float* __restrict__ A, long long ab,
             const float* __restrict__ Bm, long long bb, int K,
             float* __restrict__ C, long long cb, int ldc,
             const float* __restrict__ bias,
             const float* __restrict__ rs, const float* __restrict__ cs,
             const float* __restrict__ addp,
             float* __restrict__ C2, int ldc2)
{
    extern __shared__ char smem[];
    const int tid = threadIdx.x;
    const int lane = tid & 31, wid = tid >> 5;
    const int wm = wid & 3, wn = wid >> 2;
    const int m0 = blockIdx.x * 128, n0 = blockIdx.y * 128, bz = blockIdx.z;
    const uint32_t sb0 = su32(smem);

    const float* Ab = GATHER ? A : (A + (size_t)bz * ab);
    const float* Bb = Bm + (size_t)bz * bb;

    float c[2][8][4];
#pragma unroll
    for (int i = 0; i < 2; i++)
#pragma unroll
        for (int j = 0; j < 8; j++)
#pragma unroll
            for (int k = 0; k < 4; k++) c[i][j][k] = 0.f;

    const int nch = K / 32;
    float4 va[4], vb[4];

    auto ldg = [&](int kc) {
        const int k0 = kc * 32;
#pragma unroll
        for (int p = 0; p < 4; p++) {
            const int idx = tid + p * 256, row = idx >> 3, c4 = idx & 7;
            if (GATHER) {
                const int gm = m0 + row, b = gm >> 9, l = gm & 511;
                const int tap = kc / 24, e0 = (kc - tap * 24) * 32;
                const int src = l + tap - 1;
                va[p] = ((unsigned)src < 512u)
                    ? *reinterpret_cast<const float4*>(A + ((size_t)(b * 512 + src)) * 768 + e0 + c4 * 4)
                    : make_float4(0.f, 0.f, 0.f, 0.f);
            } else {
                va[p] = *reinterpret_cast<const float4*>(Ab + (size_t)(m0 + row) * K + k0 + c4 * 4);
            }
        }
#pragma unroll
        for (int p = 0; p < 4; p++) {
            const int idx = tid + p * 256, row = idx >> 3, c4 = idx & 7;
            vb[p] = *reinterpret_cast<const float4*>(Bb + (size_t)(n0 + row) * K + k0 + c4 * 4);
        }
    };
    auto sts = [&](int s) {
        char* sp = smem + s * STAGE;
#pragma unroll
        for (int p = 0; p < 4; p++) {
            const int idx = tid + p * 256, row = idx >> 3, c4 = idx & 7;
            const int off = row * ROWB + c4 * 8;
            float4 v = va[p];
            float hx = bfhi(v.x), hy = bfhi(v.y), hz = bfhi(v.z), hw = bfhi(v.w);
            *reinterpret_cast<uint2*>(sp + off) = make_uint2(pk2(hx, hy), pk2(hz, hw));
            *reinterpret_cast<uint2*>(sp + S_ALO + off) =
                make_uint2(pk2(v.x - hx, v.y - hy), pk2(v.z - hz, v.w - hw));
        }
#pragma unroll
        for (int p = 0; p < 4; p++) {
            const int idx = tid + p * 256, row = idx >> 3, c4 = idx & 7;
            const int off = row * ROWB + c4 * 8;
            float4 v = vb[p];
            float hx = bfhi(v.x), hy = bfhi(v.y), hz = bfhi(v.z), hw = bfhi(v.w);
            *reinterpret_cast<uint2*>(sp + S_BHI + off) = make_uint2(pk2(hx, hy), pk2(hz, hw));
            *reinterpret_cast<uint2*>(sp + S_BLO + off) =
                make_uint2(pk2(v.x - hx, v.y - hy), pk2(v.z - hz, v.w - hw));
        }
    };

    const uint32_t a_lrow = (lane & 15), a_lcol = (lane >> 4) * 8;
    const uint32_t b_lrow = (lane & 7) + ((lane >> 4) << 3), b_lcol = ((lane >> 3) & 1) * 8;

    auto compute = [&](int s) {
        const uint32_t base = sb0 + s * STAGE;
#pragma unroll
        for (int ks = 0; ks < 2; ks++) {
            const int kk = ks * 16;
            uint32_t ahi[2][4], alo[2][4];
#pragma unroll
            for (int mf = 0; mf < 2; mf++) {
                const uint32_t ra = base + (wm * 32 + mf * 16 + a_lrow) * ROWB + (kk + a_lcol) * 2;
                ldm_x4(ahi[mf], ra);
                ldm_x4(alo[mf], ra + S_ALO);
            }
#pragma unroll
            for (int nf2 = 0; nf2 < 4; nf2++) {
                uint32_t bh[4], bl[4];
                const uint32_t rb = base + S_BHI + (wn * 64 + nf2 * 16 + b_lrow) * ROWB + (kk + b_lcol) * 2;
                ldm_x4(bh, rb);
                ldm_x4(bl, rb + TILEB);
#pragma unroll
                for (int mf = 0; mf < 2; mf++) {
                    mma_bf16(c[mf][nf2 * 2 + 0], ahi[mf], bh);
                    mma_bf16(c[mf][nf2 * 2 + 1], ahi[mf], bh + 2);
                }
#pragma unroll
                for (int mf = 0; mf < 2; mf++) {
                    mma_bf16(c[mf][nf2 * 2 + 0], ahi[mf], bl);
                    mma_bf16(c[mf][nf2 * 2 + 1], ahi[mf], bl + 2);
                }
#pragma unroll
                for (int mf = 0; mf < 2; mf++) {
                    mma_bf16(c[mf][nf2 * 2 + 0], alo[mf], bh);
                    mma_bf16(c[mf][nf2 * 2 + 1], alo[mf], bh + 2);
                }
            }
        }
    };

    ldg(0);
    sts(0);
    __syncthreads();
    for (int i = 0; i < nch; i++) {
        if (i + 1 < nch) ldg(i + 1);
        compute(i & 1);
        __syncthreads();
        if (i + 1 < nch) {
            sts((i + 1) & 1);
            __syncthreads();
        }
    }

    // ---- epilogue ----
    const int tm = lane >> 2, tn = (lane & 3) * 2;
#pragma unroll
    for (int mf = 0; mf < 2; mf++) {
#pragma unroll
        for (int nf = 0; nf < 8; nf++) {
#pragma unroll
            for (int half = 0; half < 2; half++) {
                const int m = m0 + wm * 32 + mf * 16 + tm + half * 8;
                const int nn = n0 + wn * 64 + nf * 8 + tn;
                float v0 = c[mf][nf][half * 2 + 0];
                float v1 = c[mf][nf][half * 2 + 1];
                if (rs) { const float r = rs[bz * 512 + m]; v0 *= r; v1 *= r; }
                if (cs) { v0 *= cs[bz * 512 + nn]; v1 *= cs[bz * 512 + nn + 1]; }
                if (bias) {
                    v0 = fmaxf(v0 + bias[nn], 0.f);
                    v1 = fmaxf(v1 + bias[nn + 1], 0.f);
                }
                const size_t rowoff = (size_t)bz * cb + (size_t)m * ldc + nn;
                if (addp) { v0 += addp[rowoff]; v1 += addp[rowoff + 1]; }
                C[rowoff] = v0; C[rowoff + 1] = v1;
                if (C2) {
                    float* c2 = C2 + (size_t)m * ldc2 + nn;
                    c2[0] = v0; c2[1] = v1;
                }
            }
        }
    }
}

// ---------------- transpose 32x32 tiles ----------------
__global__ void transpose_k(const float* __restrict__ src, float* __restrict__ dst,
                            int rows, int cols, long long sb, long long db)
{
    __shared__ float t[32][33];
    const int b = blockIdx.z;
    const int r0 = blockIdx.y * 32, c0 = blockIdx.x * 32;
    const float* S = src + (size_t)b * sb;
    float* D = dst + (size_t)b * db;
    const int tx = threadIdx.x, ty = threadIdx.y;
#pragma unroll
    for (int k = 0; k < 32; k += 8)
        t[ty + k][tx] = S[(size_t)(r0 + ty + k) * cols + c0 + tx];
    __syncthreads();
#pragma unroll
    for (int k = 0; k < 32; k += 8)
        D[(size_t)(c0 + ty + k) * rows + r0 + tx] = t[tx][ty + k];
}

// ---------------- elementwise / reductions ----------------
__global__ void rowinv_k(const float* __restrict__ X, int D, float* __restrict__ inv)
{
    const int m = blockIdx.x, t = threadIdx.x;
    float s = 0.f;
    for (int k = t; k < D; k += 256) { float v = X[(size_t)m * D + k]; s = fmaf(v, v, s); }
    __shared__ float red[256];
    red[t] = s; __syncthreads();
    for (int st = 128; st > 0; st >>= 1) { if (t < st) red[t] += red[t + st]; __syncthreads(); }
    if (t == 0) inv[m] = rsqrtf(fmaxf(red[0], 1e-12f));
}
__global__ void exp_rowsum_k(const float* __restrict__ mask)
{
    const int row = blockIdx.x, t = threadIdx.x;
    const int b = row >> 9;
    const size_t idx = (size_t)row * L_ + t;
    float e = expf(g_G[idx]);
    g_G[idx] = e;
    float v = e * mask[b * L_ + t];
    __shared__ float red[512];
    red[t] = v; __syncthreads();
    for (int st = 256; st > 0; st >>= 1) { if (t < st) red[t] += red[t + st]; __syncthreads(); }
    if (t == 0) g_rowsum[row] = red[0];
}
__global__ void colsum_k(const float* __restrict__ src, const float* __restrict__ wmask,
                         float* __restrict__ dst)
{
    const int b = blockIdx.x, c = blockIdx.y * 128 + threadIdx.x;
    const float* S = src + (size_t)b * L_ * L_;
    float acc = 0.f;
#pragma unroll 4
    for (int r = 0; r < L_; r++) {
        float w = wmask ? wmask[b * L_ + r] : 1.f;
        acc = fmaf(S[(size_t)r * L_ + c], w, acc);
    }
    dst[b * L_ + c] = acc;
}
__global__ void a12_k(const float* __restrict__ mask)
{
    __shared__ float s[32][33];
    const int b = blockIdx.z;
    const int i0 = blockIdx.y * 32, j0 = blockIdx.x * 32;
    const int tx = threadIdx.x, ty = threadIdx.y;
    const float* Eb = g_G + (size_t)b * L_ * L_;
    const float* mk = mask + b * L_;
    s[ty][tx] = Eb[(size_t)(i0 + ty) * L_ + j0 + tx];
    __syncthreads();
    float a1 = s[ty][tx] * mk[j0 + tx] / (g_rowsum[b * L_ + i0 + ty] + EPSF) * mk[i0 + ty];
    g_A1[(size_t)b * L_ * L_ + (size_t)(i0 + ty) * L_ + j0 + tx] = a1;
    float a2 = s[tx][ty] * mk[i0 + tx] / (g_colsum[b * L_ + j0 + ty] + EPSF) * mk[j0 + ty];
    g_A2[(size_t)b * L_ * L_ + (size_t)(j0 + ty) * L_ + i0 + tx] = a2;
}
__global__ void pred3_k(const float* __restrict__ X, int D,
                        const float* __restrict__ Wd, const float* __restrict__ bd,
                        float* __restrict__ out, float* __restrict__ conf)
{
    const int m = blockIdx.x, t = threadIdx.x;
    const float* xr = X + (size_t)m * D;
    float a0 = 0.f, a1 = 0.f, a2 = 0.f;
    for (int k = t; k < D; k += 128) {
        float x = xr[k];
        a0 = fmaf(x, Wd[3 * k + 0], a0);
        a1 = fmaf(x, Wd[3 * k + 1], a1);
        a2 = fmaf(x, Wd[3 * k + 2], a2);
    }
#pragma unroll
    for (int o = 16; o > 0; o >>= 1) {
        a0 += __shfl_down_sync(0xffffffffu, a0, o);
        a1 += __shfl_down_sync(0xffffffffu, a1, o);
        a2 += __shfl_down_sync(0xffffffffu, a2, o);
    }
    __shared__ float sh[4][3];
    const int w = t >> 5, ln = t & 31;
    if (ln == 0) { sh[w][0] = a0; sh[w][1] = a1; sh[w][2] = a2; }
    __syncthreads();
    if (t == 0) {
        float p0 = sh[0][0] + sh[1][0] + sh[2][0] + sh[3][0] + bd[0];
        float p1 = sh[0][1] + sh[1][1] + sh[2][1] + sh[3][1] + bd[1];
        float p2 = sh[0][2] + sh[1][2] + sh[2][2] + sh[3][2] + bd[2];
        out[(size_t)m * 3 + 0] = p0;
        out[(size_t)m * 3 + 1] = p1;
        out[(size_t)m * 3 + 2] = p2;
        if (conf) {
            float mx = fmaxf(p0, fmaxf(p1, p2));
            float e0 = expf(p0 - mx), e1 = expf(p1 - mx), e2 = expf(p2 - mx);
            conf[m] = fmaxf(0.f, 1.f - 2.f * e0 / (e0 + e1 + e2));
        }
    }
}
__global__ void msum_k(const float* __restrict__ mask)
{
    const int b = blockIdx.x, t = threadIdx.x;
    __shared__ float red[512];
    red[t] = mask[b * L_ + t]; __syncthreads();
    for (int st = 256; st > 0; st >>= 1) { if (t < st) red[t] += red[t + st]; __syncthreads(); }
    if (t == 0) g_msum[b] = red[0];
}
__global__ void smax_combine_k(const float* __restrict__ mask)
{
    const int row = blockIdx.x, t = threadIdx.x;
    const int b = row >> 9, i = row & 511;
    const size_t base = (size_t)row * L_;
    float v = g_A2[base + t];
    __shared__ float red[512];
    red[t] = v; __syncthreads();
    for (int st = 256; st > 0; st >>= 1) { if (t < st) red[t] = fmaxf(red[t], red[t + st]); __syncthreads(); }
    const float mx = red[0]; __syncthreads();
    float e = expf(v - mx) * mask[b * L_ + t];
    red[t] = e; __syncthreads();
    for (int st = 256; st > 0; st >>= 1) { if (t < st) red[t] += red[t + st]; __syncthreads(); }
    const float sum = red[0];
    float att = e / (sum + EPSF) * mask[b * L_ + i];
    g_A2[base + t] = att + g_A1[base + t] + g_conf[row] * g_msum[b] * g_colsumP[b * L_ + t];
}

// =====================================================================
extern "C" void kernel_launch(void* const* d_in, const int* in_sizes, int n_in,
                              void* d_out, int out_size)
{
    const float* aspect_in  = (const float*)d_in[0];
    const float* opinion_in = (const float*)d_in[1];
    const float* context_in = (const float*)d_in[2];
    const float* cq   = (const float*)d_in[3];
    const float* mask = (const float*)d_in[4];
    const float* pos  = (const float*)d_in[5];
    const float* Wa = (const float*)d_in[6],  *ba = (const float*)d_in[7];
    const float* Wo = (const float*)d_in[8],  *bo = (const float*)d_in[9];
    const float* Wc = (const float*)d_in[10], *bc = (const float*)d_in[11];
    const float* Wda = (const float*)d_in[12], *bda = (const float*)d_in[13];
    const float* Wdo = (const float*)d_in[14], *bdo = (const float*)d_in[15];
    const float* Wds = (const float*)d_in[16], *bds = (const float*)d_in[17];
    float* out = (float*)d_out;

    float *aconv, *oconv, *aconvT, *oconvT, *cconvT, *posT, *WaT, *WoT, *WcT;
    float *G, *A1, *A2, *inva, *invo, *invc, *colsum, *colsumP, *conf;
    cudaGetSymbolAddress((void**)&aconv,  g_aconv);
    cudaGetSymbolAddress((void**)&oconv,  g_oconv);
    cudaGetSymbolAddress((void**)&aconvT, g_aconvT);
    cudaGetSymbolAddress((void**)&oconvT, g_oconvT);
    cudaGetSymbolAddress((void**)&cconvT, g_cconvT);
    cudaGetSymbolAddress((void**)&posT,   g_posT);
    cudaGetSymbolAddress((void**)&WaT,    g_WaT);
    cudaGetSymbolAddress((void**)&WoT,    g_WoT);
    cudaGetSymbolAddress((void**)&WcT,    g_WcT);
    cudaGetSymbolAddress((void**)&G,      g_G);
    cudaGetSymbolAddress((void**)&A1,     g_A1);
    cudaGetSymbolAddress((void**)&A2,     g_A2);
    cudaGetSymbolAddress((void**)&inva,   g_inva);
    cudaGetSymbolAddress((void**)&invo,   g_invo);
    cudaGetSymbolAddress((void**)&invc,   g_invc);
    cudaGetSymbolAddress((void**)&colsum, g_colsum);
    cudaGetSymbolAddress((void**)&colsumP,g_colsumP);
    cudaGetSymbolAddress((void**)&conf,   g_conf);

    cudaFuncSetAttribute(tc_gemm<true>,  cudaFuncAttributeMaxDynamicSharedMemorySize, SMEM_DYN);
    cudaFuncSetAttribute(tc_gemm<false>, cudaFuncAttributeMaxDynamicSharedMemorySize, SMEM_DYN);
    const dim3 tb(32, 8);

    // weight / position transposes (B operands must be K-major)
    transpose_k<<<dim3(16, 72, 1), tb>>>(Wa, WaT, 2304, 512, 0, 0);
    transpose_k<<<dim3(16, 72, 1), tb>>>(Wo, WoT, 2304, 512, 0, 0);
    transpose_k<<<dim3(24, 72, 1), tb>>>(Wc, WcT, 2304, 768, 0, 0);
    transpose_k<<<dim3(16, 16, B_), tb>>>(pos, posT, 512, 512, 512LL * 512, 512LL * 512);

    // convolutions (gathered-A GEMM, bias+relu, dual destination)
    tc_gemm<true><<<dim3(128, 4, 1), 256, SMEM_DYN>>>(
        aspect_in, 0, WaT, 0, 2304, aconv, 0, 512, ba, nullptr, nullptr, nullptr,
        out + OFF_AINT, 1024);
    tc_gemm<true><<<dim3(128, 4, 1), 256, SMEM_DYN>>>(
        opinion_in, 0, WoT, 0, 2304, oconv, 0, 512, bo, nullptr, nullptr, nullptr,
        out + OFF_OINT, 1024);
    tc_gemm<true><<<dim3(128, 6, 1), 256, SMEM_DYN>>>(
        context_in, 0, WcT, 0, 2304, out + OFF_CCONV, 0, 768, bc, nullptr, nullptr, nullptr,
        nullptr, 0);

    rowinv_k<<<M_, 256>>>(aconv, 512, inva);
    rowinv_k<<<M_, 256>>>(oconv, 512, invo);
    rowinv_k<<<M_, 256>>>(out + OFF_CCONV, 768, invc);

    // transposed conv outputs for attention-apply GEMMs (need K-major B)
    transpose_k<<<dim3(16, 16, B_), tb>>>(aconv, aconvT, 512, 512, 512LL * 512, 512LL * 512);
    transpose_k<<<dim3(16, 16, B_), tb>>>(oconv, oconvT, 512, 512, 512LL * 512, 512LL * 512);
    transpose_k<<<dim3(24, 16, B_), tb>>>(out + OFF_CCONV, cconvT, 512, 768, 512LL * 768, 512LL * 768);

    // gram with fused l2-norm scaling
    tc_gemm<false><<<dim3(4, 4, B_), 256, SMEM_DYN>>>(
        aconv, 512LL * 512, oconv, 512LL * 512, 512, G, 512LL * 512, 512,
        nullptr, inva, invo, nullptr, nullptr, 0);
    exp_rowsum_k<<<M_, 512>>>(mask);
    colsum_k<<<dim3(B_, 4), 128>>>(G, mask, colsum);
    a12_k<<<dim3(16, 16, B_), dim3(32, 32)>>>(mask);

    // attention-weighted halves of interacts
    tc_gemm<false><<<dim3(4, 4, B_), 256, SMEM_DYN>>>(
        A1, 512LL * 512, oconvT, 512LL * 512, 512, out + OFF_AINT + 512, 512LL * 1024, 1024,
        nullptr, nullptr, nullptr, nullptr, nullptr, 0);
    tc_gemm<false><<<dim3(4, 4, B_), 256, SMEM_DYN>>>(
        A2, 512LL * 512, aconvT, 512LL * 512, 512, out + OFF_OINT + 512, 512LL * 1024, 1024,
        nullptr, nullptr, nullptr, nullptr, nullptr, 0);

    pred3_k<<<M_, 128>>>(out + OFF_AINT, 1024, Wda, bda, out + OFF_APRED, nullptr);
    pred3_k<<<M_, 128>>>(out + OFF_OINT, 1024, Wdo, bdo, out + OFF_OPRED, conf);

    colsum_k<<<dim3(B_, 4), 128>>>(pos, nullptr, colsumP);
    msum_k<<<B_, 512>>>(mask);

    // context attention
    tc_gemm<false><<<dim3(4, 4, B_), 256, SMEM_DYN>>>(
        cq, 512LL * 768, out + OFF_CCONV, 512LL * 768, 768, G, 512LL * 512, 512,
        nullptr, nullptr, invc, nullptr, nullptr, 0);
    tc_gemm<false><<<dim3(4, 4, B_), 256, SMEM_DYN>>>(
        G, 512LL * 512, posT, 512LL * 512, 512, A2, 512LL * 512, 512,
        nullptr, nullptr, nullptr, nullptr, nullptr, 0);
    smax_combine_k<<<M_, 512>>>(mask);
    tc_gemm<false><<<dim3(4, 6, B_), 256, SMEM_DYN>>>(
        A2, 512LL * 512, cconvT, 768LL * 512, 512, out + OFF_CINT, 512LL * 768, 768,
        nullptr, nullptr, nullptr, cq, nullptr, 0);
    pred3_k<<<M_, 128>>>(out + OFF_CINT, 768, Wds, bds, out + OFF_SPRED, nullptr);
}

// round 5
// speedup vs baseline: 3.6340x; 1.8241x over previous
#include <cuda_runtime.h>
#include <cuda_fp16.h>
#include <cstdint>
#include <cstddef>

#define B_  32
#define L_  512
#define E_  768
#define F_  512
#define M_  (B_ * L_)
#define EPSF 1e-7f

#define OFF_APRED 0L
#define OFF_OPRED 49152L
#define OFF_SPRED 98304L
#define OFF_AINT  147456L
#define OFF_OINT  16924672L
#define OFF_CINT  33701888L
#define OFF_CCONV 46284800L

__device__ float g_aconv [(size_t)M_ * F_];
__device__ float g_oconv [(size_t)M_ * F_];
__device__ float g_G [(size_t)B_ * L_ * L_];
__device__ float g_A1[(size_t)B_ * L_ * L_];
__device__ float g_A2[(size_t)B_ * L_ * L_];
__device__ float g_inva[M_], g_invo[M_], g_invc[M_];
__device__ float g_rowsum[M_], g_colsum[M_], g_colsumP[M_];
__device__ float g_msum[B_];
__device__ float g_conf[M_];
__device__ float g_q[(size_t)B_ * E_];

// ---------------- helpers ----------------
__device__ __forceinline__ uint32_t su32(const void* p) {
    uint32_t a;
    asm("{ .reg .u64 t; cvta.to.shared.u64 t, %1; cvt.u32.u64 %0, t; }" : "=r"(a) : "l"(p));
    return a;
}
__device__ __forceinline__ void ldm_x4(uint32_t* r, uint32_t addr) {
    asm volatile("ldmatrix.sync.aligned.m8n8.x4.shared.b16 {%0,%1,%2,%3}, [%4];"
                 : "=r"(r[0]), "=r"(r[1]), "=r"(r[2]), "=r"(r[3]) : "r"(addr));
}
__device__ __forceinline__ void ldm_x4t(uint32_t* r, uint32_t addr) {
    asm volatile("ldmatrix.sync.aligned.m8n8.x4.trans.shared.b16 {%0,%1,%2,%3}, [%4];"
                 : "=r"(r[0]), "=r"(r[1]), "=r"(r[2]), "=r"(r[3]) : "r"(addr));
}
__device__ __forceinline__ void mma_f16(float* c, const uint32_t* a, const uint32_t* b) {
    asm volatile(
        "mma.sync.aligned.m16n8k16.row.col.f32.f16.f16.f32 "
        "{%0,%1,%2,%3}, {%4,%5,%6,%7}, {%8,%9}, {%0,%1,%2,%3};"
        : "+f"(c[0]), "+f"(c[1]), "+f"(c[2]), "+f"(c[3])
        : "r"(a[0]), "r"(a[1]), "r"(a[2]), "r"(a[3]), "r"(b[0]), "r"(b[1]));
}
__device__ __forceinline__ uint32_t pkh(float x, float y) {
    __half2 t = __floats2half2_rn(x, y);
    return *reinterpret_cast<uint32_t*>(&t);
}

// ---------------- fp16 tensor-core GEMM ----------------
// C[128x128] = A[M,K](row) @ B^T where B is:
//   BNN=false: [N,K] row-major (NT)        BNN=true: [K,N] row-major (NN, trans ldmatrix)
// GATHER: A gathered from X[B,512,768] with conv tap shift (K=2304).
#define AROWB 80            // 32 fp16 = 64B + 16 pad
#define NROWB 272           // 128 fp16 = 256B + 16 pad
#define S_B   10240
#define STAGE 20480
#define SMEM_DYN (2 * STAGE)

template<bool GATHER, bool BNN>
__global__ __launch_bounds__(256)
void tc_gemm(const float* __restrict__ A, long long ab,
             const float* __restrict__ Bm, long long bb, int ldb, int K,
             float* __restrict__ C, long long cb, int ldc,
             const float* __restrict__ bias,
             const float* __restrict__ rs, const float* __restrict__ cs,
             const float* __restrict__ addp,
             const float* __restrict__ rowv, const float* __restrict__ colv,
             float* __restrict__ C2, int ldc2)
{
    extern __shared__ char smem[];
    const int tid = threadIdx.x;
    const int lane = tid & 31, wid = tid >> 5;
    const int wm = wid & 3, wn = wid >> 2;
    const int m0 = blockIdx.x * 128, n0 = blockIdx.y * 128, bz = blockIdx.z;
    const uint32_t sb0 = su32(smem);

    const float* Ab = GATHER ? A : (A + (size_t)bz * ab);
    const float* Bb = Bm + (size_t)bz * bb;

    float c[2][8][4];
#pragma unroll
    for (int i = 0; i < 2; i++)
#pragma unroll
        for (int j = 0; j < 8; j++)
#pragma unroll
            for (int k = 0; k < 4; k++) c[i][j][k] = 0.f;

    const int nch = K / 32;
    float4 va[4], vb[4];

    auto ldg = [&](int kc) {
        const int k0 = kc * 32;
#pragma unroll
        for (int p = 0; p < 4; p++) {
            const int idx = tid + p * 256, row = idx >> 3, c4 = idx & 7;
            if (GATHER) {
                const int gm = m0 + row, b = gm >> 9, l = gm & 511;
                const int tap = kc / 24, e0 = (kc - tap * 24) * 32;
                const int src = l + tap - 1;
                va[p] = ((unsigned)src < 512u)
                    ? *reinterpret_cast<const float4*>(A + ((size_t)(b * 512 + src)) * 768 + e0 + c4 * 4)
                    : make_float4(0.f, 0.f, 0.f, 0.f);
            } else {
                va[p] = *reinterpret_cast<const float4*>(Ab + (size_t)(m0 + row) * K + k0 + c4 * 4);
            }
        }
        if (BNN) {
#pragma unroll
            for (int p = 0; p < 4; p++) {
                const int idx = tid + p * 256, krow = idx >> 5, c4 = idx & 31;
                vb[p] = *reinterpret_cast<const float4*>(Bb + (size_t)(k0 + krow) * ldb + n0 + c4 * 4);
            }
        } else {
#pragma unroll
            for (int p = 0; p < 4; p++) {
                const int idx = tid + p * 256, row = idx >> 3, c4 = idx & 7;
                vb[p] = *reinterpret_cast<const float4*>(Bb + (size_t)(n0 + row) * ldb + k0 + c4 * 4);
            }
        }
    };
    auto sts = [&](int s) {
        char* sp = smem + s * STAGE;
#pragma unroll
        for (int p = 0; p < 4; p++) {
            const int idx = tid + p * 256, row = idx >> 3, c4 = idx & 7;
            float4 v = va[p];
            *reinterpret_cast<uint2*>(sp + row * AROWB + c4 * 8) =
                make_uint2(pkh(v.x, v.y), pkh(v.z, v.w));
        }
        if (BNN) {
#pragma unroll
            for (int p = 0; p < 4; p++) {
                const int idx = tid + p * 256, krow = idx >> 5, c4 = idx & 31;
                float4 v = vb[p];
                *reinterpret_cast<uint2*>(sp + S_B + krow * NROWB + c4 * 8) =
                    make_uint2(pkh(v.x, v.y), pkh(v.z, v.w));
            }
        } else {
#pragma unroll
            for (int p = 0; p < 4; p++) {
                const int idx = tid + p * 256, row = idx >> 3, c4 = idx & 7;
                float4 v = vb[p];
                *reinterpret_cast<uint2*>(sp + S_B + row * AROWB + c4 * 8) =
                    make_uint2(pkh(v.x, v.y), pkh(v.z, v.w));
            }
        }
    };

    const uint32_t a_lrow = (lane & 15), a_lcol = (lane >> 4) * 8;
    const uint32_t nt_lrow = (lane & 7) + ((lane >> 4) << 3), nt_lcol = ((lane >> 3) & 1) * 8;
    const uint32_t nn_krow = (lane & 7) + (((lane >> 3) & 1) << 3), nn_ncol = (lane >> 4) * 8;

    auto compute = [&](int s) {
        const uint32_t base = sb0 + s * STAGE;
#pragma unroll
        for (int ks = 0; ks < 2; ks++) {
            const int kk = ks * 16;
            uint32_t af[2][4];
#pragma unroll
            for (int mf = 0; mf < 2; mf++)
                ldm_x4(af[mf], base + (wm * 32 + mf * 16 + a_lrow) * AROWB + (kk + a_lcol) * 2);
#pragma unroll
            for (int nf2 = 0; nf2 < 4; nf2++) {
                uint32_t bt[4];
                if (BNN)
                    ldm_x4t(bt, base + S_B + (kk + nn_krow) * NROWB + (wn * 64 + nf2 * 16 + nn_ncol) * 2);
                else
                    ldm_x4(bt, base + S_B + (wn * 64 + nf2 * 16 + nt_lrow) * AROWB + (kk + nt_lcol) * 2);
#pragma unroll
                for (int mf = 0; mf < 2; mf++) {
                    mma_f16(c[mf][nf2 * 2 + 0], af[mf], bt);
                    mma_f16(c[mf][nf2 * 2 + 1], af[mf], bt + 2);
                }
            }
        }
    };

    ldg(0);
    sts(0);
    __syncthreads();
    for (int i = 0; i < nch; i++) {
        if (i + 1 < nch) ldg(i + 1);
        compute(i & 1);
        __syncthreads();
        if (i + 1 < nch) {
            sts((i + 1) & 1);
            __syncthreads();
        }
    }

    // ---- epilogue ----
    const int tm = lane >> 2, tn = (lane & 3) * 2;
#pragma unroll
    for (int mf = 0; mf < 2; mf++) {
#pragma unroll
        for (int nf = 0; nf < 8; nf++) {
#pragma unroll
            for (int half = 0; half < 2; half++) {
                const int m = m0 + wm * 32 + mf * 16 + tm + half * 8;
                const int nn = n0 + wn * 64 + nf * 8 + tn;
                float v0 = c[mf][nf][half * 2 + 0];
                float v1 = c[mf][nf][half * 2 + 1];
                if (rs) { const float r = rs[bz * 512 + m]; v0 *= r; v1 *= r; }
                if (cs) { v0 *= cs[bz * 512 + nn]; v1 *= cs[bz * 512 + nn + 1]; }
                if (bias) {
                    v0 = fmaxf(v0 + bias[nn], 0.f);
                    v1 = fmaxf(v1 + bias[nn + 1], 0.f);
                }
                const size_t rowoff = (size_t)bz * cb + (size_t)m * ldc + nn;
                if (addp) { v0 += addp[rowoff]; v1 += addp[rowoff + 1]; }
                if (rowv) {
                    const float rv = rowv[bz * 512 + m];
                    v0 += rv * colv[(size_t)bz * ldc + nn];
                    v1 += rv * colv[(size_t)bz * ldc + nn + 1];
                }
                C[rowoff] = v0; C[rowoff + 1] = v1;
                if (C2) {
                    float* c2 = C2 + (size_t)m * ldc2 + nn;
                    c2[0] = v0; c2[1] = v1;
                }
            }
        }
    }
}

// ---------------- elementwise / reductions ----------------
__global__ void rowinv_k(const float* __restrict__ X, int D, float* __restrict__ inv)
{
    const int m = blockIdx.x, t = threadIdx.x;
    float s = 0.f;
    for (int k = t; k < D; k += 256) { float v = X[(size_t)m * D + k]; s = fmaf(v, v, s); }
    __shared__ float red[256];
    red[t] = s; __syncthreads();
    for (int st = 128; st > 0; st >>= 1) { if (t < st) red[t] += red[t + st]; __syncthreads(); }
    if (t == 0) inv[m] = rsqrtf(fmaxf(red[0], 1e-12f));
}
__global__ void exp_rowsum_k(const float* __restrict__ mask)
{
    const int row = blockIdx.x, t = threadIdx.x;
    const int b = row >> 9;
    const size_t idx = (size_t)row * L_ + t;
    float e = expf(g_G[idx]);
    g_G[idx] = e;
    float v = e * mask[b * L_ + t];
    __shared__ float red[512];
    red[t] = v; __syncthreads();
    for (int st = 256; st > 0; st >>= 1) { if (t < st) red[t] += red[t + st]; __syncthreads(); }
    if (t == 0) g_rowsum[row] = red[0];
}
__global__ void colsum_k(const float* __restrict__ src, const float* __restrict__ wmask,
                         float* __restrict__ dst)
{
    const int b = blockIdx.x, c = blockIdx.y * 128 + threadIdx.x;
    const float* S = src + (size_t)b * L_ * L_;
    float acc = 0.f;
#pragma unroll 4
    for (int r = 0; r < L_; r++) {
        float w = wmask ? wmask[b * L_ + r] : 1.f;
        acc = fmaf(S[(size_t)r * L_ + c], w, acc);
    }
    dst[b * L_ + c] = acc;
}
// q[b,e] = msum[b] * sum_r colsumP[b,r] * cconv[b,r,e]
__global__ void qprop_k(const float* __restrict__ cconv)
{
    const int b = blockIdx.x, e = blockIdx.y * 128 + threadIdx.x;
    float acc = 0.f;
#pragma unroll 4
    for (int r = 0; r < L_; r++)
        acc = fmaf(g_colsumP[b * L_ + r], cconv[((size_t)(b * L_ + r)) * E_ + e], acc);
    g_q[b * E_ + e] = acc * g_msum[b];
}
__global__ void a12_k(const float* __restrict__ mask)
{
    __shared__ float s[32][33];
    const int b = blockIdx.z;
    const int i0 = blockIdx.y * 32, j0 = blockIdx.x * 32;
    const int tx = threadIdx.x, ty = threadIdx.y;
    const float* Eb = g_G + (size_t)b * L_ * L_;
    const float* mk = mask + b * L_;
    s[ty][tx] = Eb[(size_t)(i0 + ty) * L_ + j0 + tx];
    __syncthreads();
    float a1 = s[ty][tx] * mk[j0 + tx] / (g_rowsum[b * L_ + i0 + ty] + EPSF) * mk[i0 + ty];
    g_A1[(size_t)b * L_ * L_ + (size_t)(i0 + ty) * L_ + j0 + tx] = a1;
    float a2 = s[tx][ty] * mk[i0 + tx] / (g_colsum[b * L_ + j0 + ty] + EPSF) * mk[j0 + ty];
    g_A2[(size_t)b * L_ * L_ + (size_t)(j0 + ty) * L_ + i0 + tx] = a2;
}
__global__ void pred3_k(const float* __restrict__ X, int D,
                        const float* __restrict__ Wd, const float* __restrict__ bd,
                        float* __restrict__ out, float* __restrict__ conf)
{
    const int m = blockIdx.x, t = threadIdx.x;   // 128 threads
    const float* xr = X + (size_t)m * D;
    float a0 = 0.f, a1 = 0.f, a2 = 0.f;
    for (int k4 = t; k4 < D / 4; k4 += 128) {
        float4 x = *reinterpret_cast<const float4*>(xr + k4 * 4);
        float4 w0 = *reinterpret_cast<const float4*>(Wd + k4 * 12);
        float4 w1 = *reinterpret_cast<const float4*>(Wd + k4 * 12 + 4);
        float4 w2 = *reinterpret_cast<const float4*>(Wd + k4 * 12 + 8);
        a0 = fmaf(x.x, w0.x, a0); a1 = fmaf(x.x, w0.y, a1); a2 = fmaf(x.x, w0.z, a2);
        a0 = fmaf(x.y, w0.w, a0); a1 = fmaf(x.y, w1.x, a1); a2 = fmaf(x.y, w1.y, a2);
        a0 = fmaf(x.z, w1.z, a0); a1 = fmaf(x.z, w1.w, a1); a2 = fmaf(x.z, w2.x, a2);
        a0 = fmaf(x.w, w2.y, a0); a1 = fmaf(x.w, w2.z, a1); a2 = fmaf(x.w, w2.w, a2);
    }
#pragma unroll
    for (int o = 16; o > 0; o >>= 1) {
        a0 += __shfl_down_sync(0xffffffffu, a0, o);
        a1 += __shfl_down_sync(0xffffffffu, a1, o);
        a2 += __shfl_down_sync(0xffffffffu, a2, o);
    }
    __shared__ float sh[4][3];
    const int w = t >> 5, ln = t & 31;
    if (ln == 0) { sh[w][0] = a0; sh[w][1] = a1; sh[w][2] = a2; }
    __syncthreads();
    if (t == 0) {
        float p0 = sh[0][0] + sh[1][0] + sh[2][0] + sh[3][0] + bd[0];
        float p1 = sh[0][1] + sh[1][1] + sh[2][1] + sh[3][1] + bd[1];
        float p2 = sh[0][2] + sh[1][2] + sh[2][2] + sh[3][2] + bd[2];
        out[(size_t)m * 3 + 0] = p0;
        out[(size_t)m * 3 + 1] = p1;
        out[(size_t)m * 3 + 2] = p2;
        if (conf) {
            float mx = fmaxf(p0, fmaxf(p1, p2));
            float e0 = expf(p0 - mx), e1 = expf(p1 - mx), e2 = expf(p2 - mx);
            conf[m] = fmaxf(0.f, 1.f - 2.f * e0 / (e0 + e1 + e2));
        }
    }
}
__global__ void msum_k(const float* __restrict__ mask)
{
    const int b = blockIdx.x, t = threadIdx.x;
    __shared__ float red[512];
    red[t] = mask[b * L_ + t]; __syncthreads();
    for (int st = 256; st > 0; st >>= 1) { if (t < st) red[t] += red[t + st]; __syncthreads(); }
    if (t == 0) g_msum[b] = red[0];
}
// softmask(WS, scale=True) + A1 (propagated term handled as rank-1 in final GEMM)
__global__ void smax_combine_k(const float* __restrict__ mask)
{
    const int row = blockIdx.x, t = threadIdx.x;
    const int b = row >> 9, i = row & 511;
    const size_t base = (size_t)row * L_;
    float v = g_A2[base + t];
    __shared__ float red[512];
    red[t] = v; __syncthreads();
    for (int st = 256; st > 0; st >>= 1) { if (t < st) red[t] = fmaxf(red[t], red[t + st]); __syncthreads(); }
    const float mx = red[0]; __syncthreads();
    float e = expf(v - mx) * mask[b * L_ + t];
    red[t] = e; __syncthreads();
    for (int st = 256; st > 0; st >>= 1) { if (t < st) red[t] += red[t + st]; __syncthreads(); }
    const float sum = red[0];
    float att = e / (sum + EPSF) * mask[b * L_ + i];
    g_A2[base + t] = att + g_A1[base + t];
}

// =====================================================================
extern "C" void kernel_launch(void* const* d_in, const int* in_sizes, int n_in,
                              void* d_out, int out_size)
{
    const float* aspect_in  = (const float*)d_in[0];
    const float* opinion_in = (const float*)d_in[1];
    const float* context_in = (const float*)d_in[2];
    const float* cq   = (const float*)d_in[3];
    const float* mask = (const float*)d_in[4];
    const float* pos  = (const float*)d_in[5];
    const float* Wa = (const float*)d_in[6],  *ba = (const float*)d_in[7];
    const float* Wo = (const float*)d_in[8],  *bo = (const float*)d_in[9];
    const float* Wc = (const float*)d_in[10], *bc = (const float*)d_in[11];
    const float* Wda = (const float*)d_in[12], *bda = (const float*)d_in[13];
    const float* Wdo = (const float*)d_in[14], *bdo = (const float*)d_in[15];
    const float* Wds = (const float*)d_in[16], *bds = (const float*)d_in[17];
    float* out = (float*)d_out;

    float *aconv, *oconv, *G, *A1, *A2, *inva, *invo, *invc;
    float *colsum, *colsumP, *conf, *q;
    cudaGetSymbolAddress((void**)&aconv,  g_aconv);
    cudaGetSymbolAddress((void**)&oconv,  g_oconv);
    cudaGetSymbolAddress((void**)&G,      g_G);
    cudaGetSymbolAddress((void**)&A1,     g_A1);
    cudaGetSymbolAddress((void**)&A2,     g_A2);
    cudaGetSymbolAddress((void**)&inva,   g_inva);
    cudaGetSymbolAddress((void**)&invo,   g_invo);
    cudaGetSymbolAddress((void**)&invc,   g_invc);
    cudaGetSymbolAddress((void**)&colsum, g_colsum);
    cudaGetSymbolAddress((void**)&colsumP,g_colsumP);
    cudaGetSymbolAddress((void**)&conf,   g_conf);
    cudaGetSymbolAddress((void**)&q,      g_q);

    cudaFuncSetAttribute(tc_gemm<true, true>,   cudaFuncAttributeMaxDynamicSharedMemorySize, SMEM_DYN);
    cudaFuncSetAttribute(tc_gemm<false, true>,  cudaFuncAttributeMaxDynamicSharedMemorySize, SMEM_DYN);
    cudaFuncSetAttribute(tc_gemm<false, false>, cudaFuncAttributeMaxDynamicSharedMemorySize, SMEM_DYN);

    // convolutions: gathered A @ W[K,N] (NN), bias+relu, dual destination
    tc_gemm<true, true><<<dim3(128, 4, 1), 256, SMEM_DYN>>>(
        aspect_in, 0, Wa, 0, 512, 2304, aconv, 0, 512, ba,
        nullptr, nullptr, nullptr, nullptr, nullptr, out + OFF_AINT, 1024);
    tc_gemm<true, true><<<dim3(128, 4, 1), 256, SMEM_DYN>>>(
        opinion_in, 0, Wo, 0, 512, 2304, oconv, 0, 512, bo,
        nullptr, nullptr, nullptr, nullptr, nullptr, out + OFF_OINT, 1024);
    tc_gemm<true, true><<<dim3(128, 6, 1), 256, SMEM_DYN>>>(
        context_in, 0, Wc, 0, 768, 2304, out + OFF_CCONV, 0, 768, bc,
        nullptr, nullptr, nullptr, nullptr, nullptr, nullptr, 0);

    rowinv_k<<<M_, 256>>>(aconv, 512, inva);
    rowinv_k<<<M_, 256>>>(oconv, 512, invo);
    rowinv_k<<<M_, 256>>>(out + OFF_CCONV, 768, invc);

    // gram (NT) with fused l2-norm scaling
    tc_gemm<false, false><<<dim3(4, 4, B_), 256, SMEM_DYN>>>(
        aconv, 512LL * 512, oconv, 512LL * 512, 512, 512, G, 512LL * 512, 512,
        nullptr, inva, invo, nullptr, nullptr, nullptr, nullptr, 0);
    exp_rowsum_k<<<M_, 512>>>(mask);
    colsum_k<<<dim3(B_, 4), 128>>>(G, mask, colsum);
    a12_k<<<dim3(16, 16, B_), dim3(32, 32)>>>(mask);

    // attention-weighted halves of interacts (NN: B = conv outputs [j, f])
    tc_gemm<false, true><<<dim3(4, 4, B_), 256, SMEM_DYN>>>(
        A1, 512LL * 512, oconv, 512LL * 512, 512, 512, out + OFF_AINT + 512, 512LL * 1024, 1024,
        nullptr, nullptr, nullptr, nullptr, nullptr, nullptr, nullptr, 0);
    tc_gemm<false, true><<<dim3(4, 4, B_), 256, SMEM_DYN>>>(
        A2, 512LL * 512, aconv, 512LL * 512, 512, 512, out + OFF_OINT + 512, 512LL * 1024, 1024,
        nullptr, nullptr, nullptr, nullptr, nullptr, nullptr, nullptr, 0);

    pred3_k<<<M_, 128>>>(out + OFF_AINT, 1024, Wda, bda, out + OFF_APRED, nullptr);
    pred3_k<<<M_, 128>>>(out + OFF_OINT, 1024, Wdo, bdo, out + OFF_OPRED, conf);

    // collapsed opinion propagation (rank-1 pieces)
    colsum_k<<<dim3(B_, 4), 128>>>(pos, nullptr, colsumP);
    msum_k<<<B_, 512>>>(mask);
    qprop_k<<<dim3(B_, 6), 128>>>(out + OFF_CCONV);

    // context attention
    tc_gemm<false, false><<<dim3(4, 4, B_), 256, SMEM_DYN>>>(
        cq, 512LL * 768, out + OFF_CCONV, 512LL * 768, 768, 768, G, 512LL * 512, 512,
        nullptr, nullptr, invc, nullptr, nullptr, nullptr, nullptr, 0);
    tc_gemm<false, true><<<dim3(4, 4, B_), 256, SMEM_DYN>>>(
        G, 512LL * 512, pos, 512LL * 512, 512, 512, A2, 512LL * 512, 512,
        nullptr, nullptr, nullptr, nullptr, nullptr, nullptr, nullptr, 0);
    smax_combine_k<<<M_, 512>>>(mask);
    // context_interact = (att+A1)@cconv + cq + conf ⊗ q   (rank-1 in fp32 epilogue)
    tc_gemm<false, true><<<dim3(4, 6, B_), 256, SMEM_DYN>>>(
        A2, 512LL * 512, out + OFF_CCONV, 512LL * 768, 768, 512, out + OFF_CINT, 512LL * 768, 768,
        nullptr, nullptr, nullptr, cq, conf, q, nullptr, 0);
    pred3_k<<<M_, 128>>>(out + OFF_CINT, 768, Wds, bds, out + OFF_SPRED, nullptr);
}